// round 7
// baseline (speedup 1.0000x reference)
#include <cuda_runtime.h>
#include <cstdint>

#define S 16
#define D 32
#define FFNH 64
#define WARPS 16
#define THREADS 512

// ---- smem float offsets ----
#define W_QSW 0
#define W_KSW 1024
#define W_VSW 2048
#define W_OSW 3072
#define W_1A  4096
#define W_1B  5120
#define W_2SW 6144
#define B_Q   8192
#define B_K   8224
#define B_V   8256
#define B_O   8288
#define B_1   8320
#define B_2   8384
#define OFF_SCR 8416
#define SCR_FL 2560
#define SMEM_FLOATS (OFF_SCR + WARPS * SCR_FL)
#define SMEM_BYTES (SMEM_FLOATS * 4)

// warp-scratch regions (float offsets), rows padded to 20 (vsw: 36)
//  R_XT [0,640)    xT (32x20)           live: load -> O residual
//  R_QT [640,1280) qT (32x20)           live: QKV -> scores; then attnT; then yT
//  R_KT [1280,1920) kT (32x20)          live: QKV -> scores; then ctxT; then hT lo
//  R_VS [1920,2496) vsw (16x36)         live: QKV -> ctx;    then hT hi
#define R_XT 0
#define R_QT 640
#define R_KT 1280
#define R_VS 1920
#define R_AT 640
#define R_CT 1280
#define R_YT 640
#define R_HT 1280

extern __shared__ float sm[];

// ---------- packed f32x2 helpers ----------
__device__ __forceinline__ uint64_t pk2(float a, float b) {
    uint64_t r;
    asm("mov.b64 %0, {%1, %2};" : "=l"(r) : "r"(__float_as_uint(a)), "r"(__float_as_uint(b)));
    return r;
}
__device__ __forceinline__ uint64_t dup2(float a) { return pk2(a, a); }
__device__ __forceinline__ void upk2(uint64_t p, float& a, float& b) {
    uint32_t u0, u1;
    asm("mov.b64 {%0, %1}, %2;" : "=r"(u0), "=r"(u1) : "l"(p));
    a = __uint_as_float(u0); b = __uint_as_float(u1);
}
__device__ __forceinline__ uint64_t fma2(uint64_t a, uint64_t b, uint64_t c) {
    uint64_t d;
    asm("fma.rn.f32x2 %0, %1, %2, %3;" : "=l"(d) : "l"(a), "l"(b), "l"(c));
    return d;
}
__device__ __forceinline__ uint64_t add2(uint64_t a, uint64_t b) {
    uint64_t d;
    asm("add.rn.f32x2 %0, %1, %2;" : "=l"(d) : "l"(a), "l"(b));
    return d;
}
__device__ __forceinline__ uint64_t mul2(uint64_t a, uint64_t b) {
    uint64_t d;
    asm("mul.rn.f32x2 %0, %1, %2;" : "=l"(d) : "l"(a), "l"(b));
    return d;
}
__device__ __forceinline__ void lds128p(uint64_t& a, uint64_t& b, uint32_t addr) {
    asm volatile("ld.shared.v2.b64 {%0, %1}, [%2];" : "=l"(a), "=l"(b) : "r"(addr));
}
__device__ __forceinline__ void sts128p(uint32_t addr, uint64_t a, uint64_t b) {
    asm volatile("st.shared.v2.b64 [%0], {%1, %2};" :: "r"(addr), "l"(a), "l"(b));
}
__device__ __forceinline__ float ldsf(uint32_t addr) {
    float v;
    asm volatile("ld.shared.f32 %0, [%1];" : "=f"(v) : "r"(addr));
    return v;
}
__device__ __forceinline__ void lds128f(float4& v, uint32_t addr) {
    asm volatile("ld.shared.v4.f32 {%0,%1,%2,%3}, [%4];"
                 : "=f"(v.x), "=f"(v.y), "=f"(v.z), "=f"(v.w) : "r"(addr));
}
__device__ __forceinline__ float frcp(float x) {
    float r;
    asm("rcp.approx.f32 %0, %1;" : "=f"(r) : "f"(x));
    return r;
}
__device__ __forceinline__ uint64_t shfl_add2(uint64_t v, int mask) {
    uint64_t o = __shfl_xor_sync(0xffffffffu, (unsigned long long)v, mask);
    return add2(v, o);
}

__global__ __launch_bounds__(THREADS, 1)
void tinyformer_kernel(
    const float* __restrict__ X,
    const float* __restrict__ Wq, const float* __restrict__ bq,
    const float* __restrict__ Wk, const float* __restrict__ bk,
    const float* __restrict__ Wv, const float* __restrict__ bv,
    const float* __restrict__ Wo, const float* __restrict__ bo,
    const float* __restrict__ W1, const float* __restrict__ b1,
    const float* __restrict__ W2, const float* __restrict__ b2,
    float* __restrict__ Out, int B)
{
    const int tid = threadIdx.x;

    // ---- build swizzled weights: w_sw[j][og*4+m] = W[j][og+8m] ----
    for (int i = tid; i < 1024; i += THREADS) {
        const int j = i >> 5, c = i & 31, ogb = c >> 2, mb = c & 3;
        const int src = j * 32 + ogb + 8 * mb;
        sm[W_QSW + i] = Wq[src];
        sm[W_KSW + i] = Wk[src];
        sm[W_VSW + i] = Wv[src];
        sm[W_OSW + i] = Wo[src];
        sm[W_1A + i]  = W1[j * 64 + ogb + 8 * mb];        // f = og+8m       (0..31)
        sm[W_1B + i]  = W1[j * 64 + 32 + ogb + 8 * mb];   // f = 32+og+8m    (32..63)
    }
    for (int i = tid; i < 2048; i += THREADS) {
        const int f = i >> 5, c = i & 31, ogb = c >> 2, mb = c & 3;
        sm[W_2SW + i] = W2[f * 32 + ogb + 8 * mb];
    }
    if (tid < 32) {
        sm[B_Q + tid] = bq[tid];
        sm[B_K + tid] = bk[tid];
        sm[B_V + tid] = bv[tid];
        sm[B_O + tid] = bo[tid];
        sm[B_2 + tid] = b2[tid];
    }
    if (tid < 64) sm[B_1 + tid] = b1[tid];
    __syncthreads();

    const int lane = tid & 31;
    const int wid  = tid >> 5;
    const int sg   = lane >> 3;   // s-quad: s in [4sg, 4sg+4)
    const int og   = lane & 7;    // feature group: o = og + 8m

    const uint32_t smb  = (uint32_t)__cvta_generic_to_shared(sm);
    const uint32_t scrb = smb + (OFF_SCR + wid * SCR_FL) * 4u;
    const uint32_t a_xt = scrb + R_XT * 4u;
    const uint32_t a_qt = scrb + R_QT * 4u;
    const uint32_t a_kt = scrb + R_KT * 4u;
    const uint32_t a_vs = scrb + R_VS * 4u;
    const uint32_t a_at = scrb + R_AT * 4u;
    const uint32_t a_ct = scrb + R_CT * 4u;
    const uint32_t a_yt = scrb + R_YT * 4u;
    const uint32_t a_ht = scrb + R_HT * 4u;
    const uint32_t w_q  = smb + W_QSW * 4u;
    const uint32_t w_k  = smb + W_KSW * 4u;
    const uint32_t w_v  = smb + W_VSW * 4u;
    const uint32_t w_o  = smb + W_OSW * 4u;
    const uint32_t w_1a = smb + W_1A * 4u;
    const uint32_t w_1b = smb + W_1B * 4u;
    const uint32_t w_2  = smb + W_2SW * 4u;

    const uint64_t scl2 = dup2(0.17677669529663687f);   // 1/sqrt(32)

    // per-lane biases (one-time loads, kept in regs)
    uint64_t bqd[4], bkd[4], bvd[4], bod[4], b2d[4], b1d[8];
    #pragma unroll
    for (int m = 0; m < 4; m++) {
        bqd[m] = dup2(sm[B_Q + og + 8 * m]);
        bkd[m] = dup2(sm[B_K + og + 8 * m]);
        bvd[m] = dup2(sm[B_V + og + 8 * m]);
        bod[m] = dup2(sm[B_O + og + 8 * m]);
        b2d[m] = dup2(sm[B_2 + og + 8 * m]);
    }
    #pragma unroll
    for (int m = 0; m < 8; m++) b1d[m] = dup2(sm[B_1 + og + 8 * m]);

    const int gw = blockIdx.x * WARPS + wid;
    const int nw = gridDim.x * WARPS;

    for (int b = gw; b < B; b += nw) {
        const float* xb = X + (size_t)b * (S * D);

        // ===== phase 1: load x (lane owns column `lane`), store xT rows =====
        {
            float xr[S];
            #pragma unroll
            for (int s = 0; s < S; s++) xr[s] = xb[s * D + lane];
            const uint32_t xrow = a_xt + lane * 80u;   // 20 floats * 4B
            #pragma unroll
            for (int c = 0; c < 4; c++)
                sts128p(xrow + c * 16u,
                        pk2(xr[4 * c], xr[4 * c + 1]),
                        pk2(xr[4 * c + 2], xr[4 * c + 3]));
        }
        __syncwarp();   // S1

        // ===== phase 2: fused QKV (tile: lane owns 4s x 4o per matrix) =====
        uint64_t qa[4][2], ka[4][2], va[4][2];
        #pragma unroll
        for (int m = 0; m < 4; m++) {
            qa[m][0] = bqd[m]; qa[m][1] = bqd[m];
            ka[m][0] = bkd[m]; ka[m][1] = bkd[m];
            va[m][0] = bvd[m]; va[m][1] = bvd[m];
        }
        #pragma unroll 4
        for (int j = 0; j < D; j++) {
            uint64_t x0, x1;
            lds128p(x0, x1, a_xt + j * 80u + sg * 16u);
            float4 wq4, wk4, wv4;
            lds128f(wq4, w_q + j * 128u + og * 16u);
            lds128f(wk4, w_k + j * 128u + og * 16u);
            lds128f(wv4, w_v + j * 128u + og * 16u);
            const float* q4 = (const float*)&wq4;
            const float* k4 = (const float*)&wk4;
            const float* v4 = (const float*)&wv4;
            #pragma unroll
            for (int m = 0; m < 4; m++) {
                const uint64_t wq2 = dup2(q4[m]), wk2 = dup2(k4[m]), wv2 = dup2(v4[m]);
                qa[m][0] = fma2(x0, wq2, qa[m][0]); qa[m][1] = fma2(x1, wq2, qa[m][1]);
                ka[m][0] = fma2(x0, wk2, ka[m][0]); ka[m][1] = fma2(x1, wk2, ka[m][1]);
                va[m][0] = fma2(x0, wv2, va[m][0]); va[m][1] = fma2(x1, wv2, va[m][1]);
            }
        }
        // scale q by 1/sqrt(D); stage qT, kT (feature-major rows)
        #pragma unroll
        for (int m = 0; m < 4; m++) {
            qa[m][0] = mul2(qa[m][0], scl2);
            qa[m][1] = mul2(qa[m][1], scl2);
            const uint32_t off = (og + 8 * m) * 80u + sg * 16u;
            sts128p(a_qt + off, qa[m][0], qa[m][1]);
            sts128p(a_kt + off, ka[m][0], ka[m][1]);
        }
        // stage v swizzled token-major: vsw[t][og*4+m] = v[t][og+8m]
        {
            float vf[4][4];   // [m][token i]
            #pragma unroll
            for (int m = 0; m < 4; m++) {
                upk2(va[m][0], vf[m][0], vf[m][1]);
                upk2(va[m][1], vf[m][2], vf[m][3]);
            }
            #pragma unroll
            for (int i = 0; i < 4; i++)
                sts128p(a_vs + ((4 * sg + i) * 36u + og * 4u) * 4u,
                        pk2(vf[0][i], vf[1][i]), pk2(vf[2][i], vf[3][i]));
        }
        __syncwarp();   // S2

        // ===== phase 3: scores (lane owns 4s x {t=og, t=og+8}) =====
        uint64_t sc[2][2] = {{0ull, 0ull}, {0ull, 0ull}};
        #pragma unroll 4
        for (int d = 0; d < D; d++) {
            uint64_t q0, q1;
            lds128p(q0, q1, a_qt + d * 80u + sg * 16u);
            const uint64_t k0 = dup2(ldsf(a_kt + (d * 20 + og) * 4u));
            const uint64_t k1 = dup2(ldsf(a_kt + (d * 20 + og + 8) * 4u));
            sc[0][0] = fma2(q0, k0, sc[0][0]); sc[0][1] = fma2(q1, k0, sc[0][1]);
            sc[1][0] = fma2(q0, k1, sc[1][0]); sc[1][1] = fma2(q1, k1, sc[1][1]);
        }
        __syncwarp();   // S3: all qT/kT reads done before attnT overwrites R_QT

        // ===== phase 4: softmax over t (no max-sub: |score| small) =====
        {
            float e[2][4];
            #pragma unroll
            for (int n = 0; n < 2; n++) {
                float f0, f1;
                upk2(sc[n][0], f0, f1);
                e[n][0] = __expf(f0); e[n][1] = __expf(f1);
                upk2(sc[n][1], f0, f1);
                e[n][2] = __expf(f0); e[n][3] = __expf(f1);
            }
            uint64_t ps0 = pk2(e[0][0] + e[1][0], e[0][1] + e[1][1]);
            uint64_t ps1 = pk2(e[0][2] + e[1][2], e[0][3] + e[1][3]);
            ps0 = shfl_add2(ps0, 1); ps1 = shfl_add2(ps1, 1);
            ps0 = shfl_add2(ps0, 2); ps1 = shfl_add2(ps1, 2);
            ps0 = shfl_add2(ps0, 4); ps1 = shfl_add2(ps1, 4);
            float s0, s1, s2, s3;
            upk2(ps0, s0, s1); upk2(ps1, s2, s3);
            const uint64_t rs0 = pk2(frcp(s0), frcp(s1));
            const uint64_t rs1 = pk2(frcp(s2), frcp(s3));
            #pragma unroll
            for (int n = 0; n < 2; n++) {
                const uint64_t a0 = mul2(pk2(e[n][0], e[n][1]), rs0);
                const uint64_t a1 = mul2(pk2(e[n][2], e[n][3]), rs1);
                sts128p(a_at + ((og + 8 * n) * 20u + sg * 4u) * 4u, a0, a1);
            }
        }
        __syncwarp();   // S4

        // ===== phase 5: context = attn @ v (lane owns 4s x 4d) =====
        uint64_t cx[4][2];
        #pragma unroll
        for (int m = 0; m < 4; m++) { cx[m][0] = 0ull; cx[m][1] = 0ull; }
        #pragma unroll 4
        for (int t = 0; t < S; t++) {
            uint64_t a0, a1;
            lds128p(a0, a1, a_at + t * 80u + sg * 16u);
            float4 v4;
            lds128f(v4, a_vs + (t * 36u + og * 4u) * 4u);
            const float* vv = (const float*)&v4;
            #pragma unroll
            for (int m = 0; m < 4; m++) {
                const uint64_t v2 = dup2(vv[m]);
                cx[m][0] = fma2(a0, v2, cx[m][0]);
                cx[m][1] = fma2(a1, v2, cx[m][1]);
            }
        }
        #pragma unroll
        for (int m = 0; m < 4; m++)
            sts128p(a_ct + ((og + 8 * m) * 20u + sg * 4u) * 4u, cx[m][0], cx[m][1]);
        __syncwarp();   // S5

        // ===== phase 6: O projection + residual 1 =====
        uint64_t ya[4][2];
        #pragma unroll
        for (int m = 0; m < 4; m++) { ya[m][0] = bod[m]; ya[m][1] = bod[m]; }
        #pragma unroll 4
        for (int j = 0; j < D; j++) {
            uint64_t c0, c1;
            lds128p(c0, c1, a_ct + j * 80u + sg * 16u);
            float4 wo4;
            lds128f(wo4, w_o + j * 128u + og * 16u);
            const float* o4 = (const float*)&wo4;
            #pragma unroll
            for (int m = 0; m < 4; m++) {
                const uint64_t w2v = dup2(o4[m]);
                ya[m][0] = fma2(c0, w2v, ya[m][0]);
                ya[m][1] = fma2(c1, w2v, ya[m][1]);
            }
        }
        // residual: x tile re-read from xT
        #pragma unroll
        for (int m = 0; m < 4; m++) {
            uint64_t x0, x1;
            lds128p(x0, x1, a_xt + ((og + 8 * m) * 20u + sg * 4u) * 4u);
            ya[m][0] = add2(ya[m][0], x0);
            ya[m][1] = add2(ya[m][1], x1);
        }
        #pragma unroll
        for (int m = 0; m < 4; m++)
            sts128p(a_yt + ((og + 8 * m) * 20u + sg * 4u) * 4u, ya[m][0], ya[m][1]);
        __syncwarp();   // S6

        // ===== phase 7: FFN1 + ReLU (lane owns 4s x 8f) =====
        uint64_t ha[8][2];
        #pragma unroll
        for (int m = 0; m < 8; m++) { ha[m][0] = b1d[m]; ha[m][1] = b1d[m]; }
        #pragma unroll 4
        for (int j = 0; j < D; j++) {
            uint64_t y0, y1;
            lds128p(y0, y1, a_yt + j * 80u + sg * 16u);
            float4 wa4, wb4;
            lds128f(wa4, w_1a + j * 128u + og * 16u);
            lds128f(wb4, w_1b + j * 128u + og * 16u);
            const float* wa = (const float*)&wa4;
            const float* wb = (const float*)&wb4;
            #pragma unroll
            for (int m = 0; m < 4; m++) {
                const uint64_t w2a = dup2(wa[m]), w2b = dup2(wb[m]);
                ha[m][0]     = fma2(y0, w2a, ha[m][0]);
                ha[m][1]     = fma2(y1, w2a, ha[m][1]);
                ha[m + 4][0] = fma2(y0, w2b, ha[m + 4][0]);
                ha[m + 4][1] = fma2(y1, w2b, ha[m + 4][1]);
            }
        }
        #pragma unroll
        for (int m = 0; m < 8; m++) {
            float f0, f1, f2, f3;
            upk2(ha[m][0], f0, f1);
            upk2(ha[m][1], f2, f3);
            sts128p(a_ht + ((og + 8 * m) * 20u + sg * 4u) * 4u,
                    pk2(fmaxf(f0, 0.f), fmaxf(f1, 0.f)),
                    pk2(fmaxf(f2, 0.f), fmaxf(f3, 0.f)));
        }
        __syncwarp();   // S7

        // ===== phase 8: FFN2 + residual 2 -> global =====
        uint64_t za[4][2];
        #pragma unroll
        for (int m = 0; m < 4; m++) { za[m][0] = b2d[m]; za[m][1] = b2d[m]; }
        #pragma unroll 4
        for (int f = 0; f < FFNH; f++) {
            uint64_t h0, h1;
            lds128p(h0, h1, a_ht + f * 80u + sg * 16u);
            float4 w24;
            lds128f(w24, w_2 + f * 128u + og * 16u);
            const float* w4 = (const float*)&w24;
            #pragma unroll
            for (int m = 0; m < 4; m++) {
                const uint64_t w2v = dup2(w4[m]);
                za[m][0] = fma2(h0, w2v, za[m][0]);
                za[m][1] = fma2(h1, w2v, za[m][1]);
            }
        }
        float* ob = Out + (size_t)b * (S * D);
        #pragma unroll
        for (int m = 0; m < 4; m++) {
            #pragma unroll
            for (int p = 0; p < 2; p++) {
                const uint64_t z2 = add2(za[m][p], ya[m][p]);
                float z0, z1;
                upk2(z2, z0, z1);
                const int s0 = 4 * sg + 2 * p;
                ob[s0 * D + og + 8 * m]       = z0;
                ob[(s0 + 1) * D + og + 8 * m] = z1;
            }
        }
        __syncwarp();   // order hT reads before next batch's stores
    }
}

extern "C" void kernel_launch(void* const* d_in, const int* in_sizes, int n_in,
                              void* d_out, int out_size) {
    const float* X  = (const float*)d_in[0];
    const float* Wq = (const float*)d_in[1];
    const float* bq = (const float*)d_in[2];
    const float* Wk = (const float*)d_in[3];
    const float* bk = (const float*)d_in[4];
    const float* Wv = (const float*)d_in[5];
    const float* bv = (const float*)d_in[6];
    const float* Wo = (const float*)d_in[7];
    const float* bo = (const float*)d_in[8];
    const float* W1 = (const float*)d_in[9];
    const float* b1 = (const float*)d_in[10];
    const float* W2 = (const float*)d_in[11];
    const float* b2 = (const float*)d_in[12];
    float* Out = (float*)d_out;

    const int B = in_sizes[0] / (S * D);

    cudaFuncSetAttribute(tinyformer_kernel,
                         cudaFuncAttributeMaxDynamicSharedMemorySize, SMEM_BYTES);

    int blocks = 148;
    int max_blocks = (B + WARPS - 1) / WARPS;
    if (blocks > max_blocks) blocks = max_blocks;

    tinyformer_kernel<<<blocks, THREADS, SMEM_BYTES>>>(
        X, Wq, bq, Wk, bk, Wv, bv, Wo, bo, W1, b1, W2, b2, Out, B);
}